// round 5
// baseline (speedup 1.0000x reference)
#include <cuda_runtime.h>
#include <cstdint>

#define NSC   4
#define NTL   256
#define NMP   4096
#define HID   512
#define KNN   36
#define NJ    109         // 1 + 36 + 36 + 36
#define FEAT  130
#define NPAIR (NSC*NTL)

#define DCHUNK 13
#define NCHUNK 10
#define GEMM_THREADS 512

// ---------------- scratch (no allocation allowed) ----------------
__device__ float g_rpe[NPAIR*72*3];     // per (s,i): 36 tt rel-poses then 36 tm rel-poses
__device__ int   g_idx_tm[NPAIR*KNN];   // selected map-token indices
__device__ int   g_benc;                // bool encoding: 0=uint8, 1=int32, 2=float32

// ---------------- glibc sinf/cosf emulation (optimized-routines) ----------------
// Structure: |x|<0.75 fast path; else quadrant n via scaled-int conversion of
// x*(2/pi)*2^24; reduce with single-double pi/2; shared sine poly, cos poly with
// table[1] = negated coefficients (== exact negation of the table[0] result).
#define GC_HPI_INV 0x1.45F306DC9C883p+23   // 2/pi * 2^24
#define GC_HPI     0x1.921FB54442D18p0     // pi/2 (double)
#define GC_S1    (-0x1.555545995720cp-3)
#define GC_S2    ( 0x1.1107605230bc4p-7)
#define GC_S3    (-0x1.994eb3774cf24p-13)
#define GC_C1    (-0x1.ffffffd0c5e81p-2)
#define GC_C2    ( 0x1.55553e1053a42p-5)
#define GC_C3    (-0x1.6c087e80f1e27p-10)
#define GC_C4    ( 0x1.99343027bf8c3p-16)

__device__ __forceinline__ float gl_poly(double x, double x2, int t, int odd){
    double r;
    if (!odd){
        // sine: x + s1 x^3 + s2 x^5 + s3 x^7  (coeffs shared between tables)
        double x3 = x * x2;
        double s1 = GC_S2 + x2 * GC_S3;
        double x7 = x3 * x2;
        double s  = x + x3 * GC_S1;
        r = s + x7 * s1;
    } else {
        // cosine: 1 + c1 x^2 + c2 x^4 + c3 x^6 + c4 x^8; table1 computes -cos
        double x4 = x2 * x2;
        double s2 = GC_C3 + x2 * GC_C4;
        double x6 = x4 * x2;
        double s1 = GC_C1 + x2 * GC_C2;
        double s  = 1.0 + x2 * s1;
        r = s + x6 * s2;
        if (t) r = -r;
    }
    return (float)r;
}

__device__ __forceinline__ float gl_sinf(float y){
    double x = (double)y;
    float ay = fabsf(y);
    if (ay < 0.75f){
        if (ay < 2.44140625e-4f) return y;   // |y| < 2^-12
        return gl_poly(x, x*x, 0, 0);
    }
    // |y| < 120 always holds for our inputs (|yaw| <= pi)
    double rr = x * GC_HPI_INV;
    int n = (((int)rr) + 0x800000) >> 24;
    double xr = fma((double)(-n), GC_HPI, x);
    double sg = ((n + 1) & 2) ? -1.0 : 1.0;  // sign[n&3] = {1,-1,-1,1}
    int t = (n >> 1) & 1;                    // n&2 -> table1
    return gl_poly(xr * sg, xr * xr, t, n & 1);
}

__device__ __forceinline__ float gl_cosf(float y){
    double x = (double)y;
    float ay = fabsf(y);
    if (ay < 0.75f){
        if (ay < 2.44140625e-4f) return 1.0f;
        return gl_poly(x, x*x, 0, 1);
    }
    double rr = x * GC_HPI_INV;
    int n = (((int)rr) + 0x800000) >> 24;
    double xr = fma((double)(-n), GC_HPI, x);
    int n1 = n + 1;                          // cos(x) = sin(x + pi/2)
    double sg = ((n1 + 1) & 2) ? -1.0 : 1.0;
    int t = (n1 >> 1) & 1;
    return gl_poly(xr * sg, xr * xr, t, n1 & 1);
}

// ---------------- helpers ----------------
__device__ __forceinline__ float wrap_angle_f(float a){
    const float PI_F     = 3.14159265358979323846f;
    const float TWO_PI_F = 6.28318530717958647692f;
    float t = __fadd_rn(a, PI_F);
    float m = fmodf(t, TWO_PI_F);            // truncation rem (exact), == lax.rem
    if (m < 0.f) m = __fadd_rn(m, TWO_PI_F); // floor-mod adjust, matches jnp.mod
    return __fsub_rn(m, PI_F);
}

__device__ __forceinline__ unsigned long long dkey(float d, int j){
    return (((unsigned long long)__float_as_uint(d)) << 32) | (unsigned int)j;
}

__device__ __forceinline__ bool rbool(const void* p, int i){
    int e = g_benc;
    if (e == 1) return ((const int*)p)[i] != 0;
    if (e == 2) return ((const float*)p)[i] != 0.0f;
    return ((const unsigned char*)p)[i] != 0;
}

// Non-fused local-frame transform (matches XLA:CPU non-contracted mul/mul/add).
__device__ __forceinline__ void rel_pose_nf(float c, float sn,
                                            float dx, float dy,
                                            float& lx, float& ly){
    lx = __fadd_rn(__fmul_rn(c,  dx), __fmul_rn(sn, dy));
    ly = __fadd_rn(__fmul_rn(-sn, dx), __fmul_rn(c,  dy));
}
__device__ __forceinline__ float dist_nf(float dx, float dy){
    return sqrtf(__fadd_rn(__fmul_rn(dx,dx), __fmul_rn(dy,dy)));
}

__device__ __forceinline__ unsigned int smem_u32(const void* p){
    return (unsigned int)__cvta_generic_to_shared(p);
}
__device__ __forceinline__ void cp_async16(unsigned int dst, const void* src){
    asm volatile("cp.async.ca.shared.global [%0], [%1], 16;\n" :: "r"(dst), "l"(src));
}
__device__ __forceinline__ void cp_commit(){ asm volatile("cp.async.commit_group;\n"); }
__device__ __forceinline__ void cp_wait_1(){ asm volatile("cp.async.wait_group 1;\n"); }
__device__ __forceinline__ void cp_wait_0(){ asm volatile("cp.async.wait_group 0;\n"); }

__device__ __forceinline__ unsigned long long pk2(float a, float b){
    unsigned long long r;
    asm("mov.b64 %0, {%1, %2};" : "=l"(r) : "f"(a), "f"(b));
    return r;
}
__device__ __forceinline__ unsigned long long fma2(unsigned long long a,
                                                   unsigned long long b,
                                                   unsigned long long c){
    unsigned long long d;
    asm("fma.rn.f32x2 %0, %1, %2, %3;" : "=l"(d) : "l"(a), "l"(b), "l"(c));
    return d;
}
__device__ __forceinline__ float2 up2(unsigned long long v){
    float2 f;
    asm("mov.b64 {%0, %1}, %2;" : "=f"(f.x), "=f"(f.y) : "l"(v));
    return f;
}

// ---------------- kernel 0: detect bool encoding ----------------
__global__ void detect_bool_kernel(const unsigned int* __restrict__ p){
    bool okI = true, okF = true;
    for (int i = 0; i < 256; i++){
        unsigned int w = p[i];
        if (w > 1u) okI = false;
        if (w != 0u && w != 0x3f800000u) okF = false;
    }
    g_benc = okI ? 1 : (okF ? 2 : 0);
}

// ---------------- kernel A: tl->tl KNN (256 candidates -> 36) ----------------
__global__ void knn_tt_kernel(const void* __restrict__ tl_valid,
                              const float* __restrict__ tl_pose)
{
    __shared__ unsigned long long keys[NTL];
    __shared__ unsigned long long wpart[8];
    __shared__ int sel[KNN];

    int pair = blockIdx.x;
    int s    = pair >> 8;
    int tid  = threadIdx.x;

    float sx = tl_pose[pair*3+0], sy = tl_pose[pair*3+1], syaw = tl_pose[pair*3+2];
    bool sinv = !rbool(tl_valid, pair);

    {
        int j = tid;
        float tx = tl_pose[(s*NTL+j)*3+0], ty = tl_pose[(s*NTL+j)*3+1];
        float dx = __fsub_rn(tx, sx), dy = __fsub_rn(ty, sy);
        float dist = dist_nf(dx, dy);
        if (sinv || !rbool(tl_valid, s*NTL+j)) dist = 1e6f;
        keys[j] = dkey(dist, j);
    }
    __syncthreads();

    int lane = tid & 31, wid = tid >> 5;
    for (int k = 0; k < KNN; k++){
        unsigned long long v = keys[tid];
        #pragma unroll
        for (int off = 16; off; off >>= 1){
            unsigned long long o = __shfl_xor_sync(0xffffffffu, v, off);
            v = (o < v) ? o : v;
        }
        if (lane == 0) wpart[wid] = v;
        __syncthreads();
        if (tid == 0){
            unsigned long long m = wpart[0];
            #pragma unroll
            for (int w = 1; w < 8; w++) m = (wpart[w] < m) ? wpart[w] : m;
            int ji = (int)(m & 0xffffffffull);
            sel[k] = ji;
            keys[ji] = 0xffffffffffffffffull;
        }
        __syncthreads();
    }

    if (tid < KNN){
        int ji = sel[tid];
        float c  = gl_cosf(syaw);
        float sn = gl_sinf(syaw);
        float tx = tl_pose[(s*NTL+ji)*3+0], ty = tl_pose[(s*NTL+ji)*3+1], tyaw = tl_pose[(s*NTL+ji)*3+2];
        float dx = __fsub_rn(tx, sx), dy = __fsub_rn(ty, sy);
        float lx, ly;
        rel_pose_nf(c, sn, dx, dy, lx, ly);
        float dyaw = wrap_angle_f(__fsub_rn(tyaw, syaw));
        int base = (pair*72 + tid)*3;
        g_rpe[base+0] = lx; g_rpe[base+1] = ly; g_rpe[base+2] = dyaw;
    }
}

// ---------------- kernel B: tl->mp KNN (4096 candidates -> 36) ----------------
__global__ void knn_tm_kernel(const void* __restrict__ tl_valid,
                              const float* __restrict__ tl_pose,
                              const void* __restrict__ mp_invalid,
                              const float* __restrict__ mp_pose)
{
    __shared__ unsigned long long keys[NMP];
    __shared__ unsigned long long wpart[16];
    __shared__ int sel[KNN];

    int pair = blockIdx.x;
    int s    = pair >> 8;
    int tid  = threadIdx.x;   // 512

    float sx = tl_pose[pair*3+0], sy = tl_pose[pair*3+1], syaw = tl_pose[pair*3+2];
    bool sinv = !rbool(tl_valid, pair);

    for (int j = tid; j < NMP; j += 512){
        float tx = mp_pose[(s*NMP+j)*3+0], ty = mp_pose[(s*NMP+j)*3+1];
        float dx = __fsub_rn(tx, sx), dy = __fsub_rn(ty, sy);
        float dist = dist_nf(dx, dy);
        if (sinv || rbool(mp_invalid, s*NMP+j)) dist = 1e6f;
        keys[j] = dkey(dist, j);
    }
    __syncthreads();

    int lane = tid & 31, wid = tid >> 5;
    for (int k = 0; k < KNN; k++){
        unsigned long long v = 0xffffffffffffffffull;
        #pragma unroll
        for (int q = 0; q < 8; q++){
            unsigned long long o = keys[tid + q*512];
            v = (o < v) ? o : v;
        }
        #pragma unroll
        for (int off = 16; off; off >>= 1){
            unsigned long long o = __shfl_xor_sync(0xffffffffu, v, off);
            v = (o < v) ? o : v;
        }
        if (lane == 0) wpart[wid] = v;
        __syncthreads();
        if (tid == 0){
            unsigned long long m = wpart[0];
            #pragma unroll
            for (int w = 1; w < 16; w++) m = (wpart[w] < m) ? wpart[w] : m;
            int ji = (int)(m & 0xffffffffull);
            sel[k] = ji;
            keys[ji] = 0xffffffffffffffffull;
        }
        __syncthreads();
    }

    if (tid < KNN){
        int ji = sel[tid];
        float c  = gl_cosf(syaw);
        float sn = gl_sinf(syaw);
        float tx = mp_pose[(s*NMP+ji)*3+0], ty = mp_pose[(s*NMP+ji)*3+1], tyaw = mp_pose[(s*NMP+ji)*3+2];
        float dx = __fsub_rn(tx, sx), dy = __fsub_rn(ty, sy);
        float lx, ly;
        rel_pose_nf(c, sn, dx, dy, lx, ly);
        float dyaw = wrap_angle_f(__fsub_rn(tyaw, syaw));
        int base = (pair*72 + 36 + tid)*3;
        g_rpe[base+0] = lx; g_rpe[base+1] = ly; g_rpe[base+2] = dyaw;
        g_idx_tm[pair*KNN + tid] = ji;
    }
}

// ---------------- kernel C: feature gathers (j=0 and j=37..72) ----------------
__global__ void gather_copy_kernel(const int* __restrict__ tl_attr,
                                   const float* __restrict__ mp_feat,
                                   float* __restrict__ out)
{
    __shared__ int rows[37];
    int pair = blockIdx.x;
    int s    = pair >> 8;
    int tid  = threadIdx.x;   // 256

    if (tid == 0)        rows[0]   = tl_attr[pair];
    else if (tid < 37)   rows[tid] = g_idx_tm[pair*KNN + tid - 1];
    __syncthreads();

    const float4* src4 = (const float4*)mp_feat;
    float4*       out4 = (float4*)out;
    for (int q = tid; q < 37*128; q += 256){
        int rr = q >> 7;          // which of the 37 rows
        int w  = q & 127;         // float4 within the row
        int srow = rows[rr];
        int j = (rr == 0) ? 0 : (36 + rr);   // 0 or 37..72
        out4[((long)(pair*NJ + j))*128 + w] = src4[((long)(s*NMP + srow))*128 + w];
    }
}

// ---------------- kernel D: RPE embedding GEMM (72 x 130 x 512 per block) ----------------
__global__ void __launch_bounds__(GEMM_THREADS)
rpe_gemm_kernel(const float* __restrict__ W,
                const float* __restrict__ bvec,
                float* __restrict__ out)
{
    extern __shared__ float sm[];
    float* featT = sm;                    // [130][76] transposed features
    float* wbuf  = sm + FEAT*76;          // [2][13][512] W double buffer
    __shared__ float rp[72][3];

    int pair = blockIdx.x;
    int tid  = threadIdx.x;

    if (tid < 216) rp[tid/3][tid%3] = g_rpe[pair*216 + tid];

    // prefetch W chunk 0 while features are computed
    {
        unsigned int wb0 = smem_u32(wbuf);
        const float* src = W;
        for (int q = tid; q < (DCHUNK*HID)/4; q += GEMM_THREADS)
            cp_async16(wb0 + q*16, src + q*4);
        cp_commit();
    }
    __syncthreads();   // rp ready

    // feature matrix: d in [0,64)=sin(x f / y f), [64,128)=cos, 128=cos(yaw), 129=sin(yaw)
    for (int task = tid; task < 72*65; task += GEMM_THREADS){
        int r = task / 65;
        int t = task - r*65;
        if (t < 64){
            int isY = t >> 5;
            int f   = t & 31;
            float v   = rp[r][isY];
            float ang = v * __int_as_float((127 + f) << 23);  // exact *2^f
            featT[t*76 + r]        = sinf(ang);
            featT[(64 + t)*76 + r] = cosf(ang);
        } else {
            float yv = rp[r][2];
            featT[128*76 + r] = gl_cosf(yv);
            featT[129*76 + r] = gl_sinf(yv);
        }
    }

    int colt = tid & 63;        // 64 col tiles of 8
    int rowt = tid >> 6;        // 8 row tiles of 9
    int c0 = colt * 8;
    int r0 = rowt * 9;

    unsigned long long acc[9][4];
    {
        float4 b0 = *(const float4*)(bvec + c0);
        float4 b1 = *(const float4*)(bvec + c0 + 4);
        unsigned long long p0 = pk2(b0.x,b0.y), p1 = pk2(b0.z,b0.w);
        unsigned long long p2 = pk2(b1.x,b1.y), p3 = pk2(b1.z,b1.w);
        #pragma unroll
        for (int r = 0; r < 9; r++){
            acc[r][0]=p0; acc[r][1]=p1; acc[r][2]=p2; acc[r][3]=p3;
        }
    }

    for (int ch = 0; ch < NCHUNK; ch++){
        if (ch + 1 < NCHUNK){
            unsigned int wb = smem_u32(wbuf + ((ch+1)&1)*DCHUNK*HID);
            const float* src = W + (ch+1)*DCHUNK*HID;
            for (int q = tid; q < (DCHUNK*HID)/4; q += GEMM_THREADS)
                cp_async16(wb + q*16, src + q*4);
            cp_commit();
            cp_wait_1();
        } else {
            cp_wait_0();
        }
        __syncthreads();   // chunk ch present; (iter 0) featT also ready

        const float* wbp = wbuf + (ch&1)*DCHUNK*HID;
        #pragma unroll
        for (int dd = 0; dd < DCHUNK; dd++){
            const float* fr = featT + (ch*DCHUNK + dd)*76 + r0;
            const float4* wp = (const float4*)(wbp + dd*HID + c0);
            float4 wA = wp[0], wB = wp[1];
            unsigned long long w01 = pk2(wA.x, wA.y);
            unsigned long long w23 = pk2(wA.z, wA.w);
            unsigned long long w45 = pk2(wB.x, wB.y);
            unsigned long long w67 = pk2(wB.z, wB.w);
            #pragma unroll
            for (int r = 0; r < 9; r++){
                float fv = fr[r];
                unsigned long long fp = pk2(fv, fv);
                acc[r][0] = fma2(fp, w01, acc[r][0]);
                acc[r][1] = fma2(fp, w23, acc[r][1]);
                acc[r][2] = fma2(fp, w45, acc[r][2]);
                acc[r][3] = fma2(fp, w67, acc[r][3]);
            }
        }
        __syncthreads();   // protect buffer before next chunk's cp.async overwrites
    }

    float4* out4 = (float4*)out;
    #pragma unroll
    for (int r = 0; r < 9; r++){
        int row = r0 + r;                        // 0..71
        int j = (row < 36) ? (1 + row) : (37 + row);   // 1..36 (tt) / 73..108 (tm)
        float2 a = up2(acc[r][0]), b2 = up2(acc[r][1]);
        float2 c2 = up2(acc[r][2]), d2 = up2(acc[r][3]);
        long off = (((long)(pair*NJ + j))*HID + c0) >> 2;
        out4[off]   = make_float4(a.x, a.y, b2.x, b2.y);
        out4[off+1] = make_float4(c2.x, c2.y, d2.x, d2.y);
    }
}

// ---------------- host ----------------
extern "C" void kernel_launch(void* const* d_in, const int* in_sizes, int n_in,
                              void* d_out, int out_size)
{
    // defaults in setup_inputs order
    const void*          tl_valid   = d_in[0];
    const int*           tl_attr    = (const int*)d_in[1];
    const float*         tl_pose    = (const float*)d_in[2];
    const void*          mp_invalid = d_in[3];
    const float*         mp_feat    = (const float*)d_in[4];
    const float*         mp_pose    = (const float*)d_in[5];
    const float*         W          = (const float*)d_in[6];
    const float*         b          = (const float*)d_in[7];

    // defensive remap by unique element counts (the two 1024-sized entries keep dict order)
    for (int i = 0; i < n_in; i++){
        int sz = in_sizes[i];
        if      (sz == NSC*NTL*3)    tl_pose    = (const float*)d_in[i];
        else if (sz == NSC*NMP)      mp_invalid = d_in[i];
        else if (sz == NSC*NMP*HID)  mp_feat    = (const float*)d_in[i];
        else if (sz == NSC*NMP*3)    mp_pose    = (const float*)d_in[i];
        else if (sz == FEAT*HID)     W          = (const float*)d_in[i];
        else if (sz == HID)          b          = (const float*)d_in[i];
    }

    float* out = (float*)d_out;
    (void)out_size;

    detect_bool_kernel<<<1, 1>>>((const unsigned int*)tl_valid);
    knn_tt_kernel<<<NPAIR, 256>>>(tl_valid, tl_pose);
    knn_tm_kernel<<<NPAIR, 512>>>(tl_valid, tl_pose, mp_invalid, mp_pose);
    gather_copy_kernel<<<NPAIR, 256>>>(tl_attr, mp_feat, out);

    size_t smem = (size_t)(FEAT*76 + 2*DCHUNK*HID) * sizeof(float);  // 92,768 B
    cudaFuncSetAttribute(rpe_gemm_kernel,
                         cudaFuncAttributeMaxDynamicSharedMemorySize, (int)smem);
    rpe_gemm_kernel<<<NPAIR, GEMM_THREADS, smem>>>(W, b, out);
}